// round 9
// baseline (speedup 1.0000x reference)
#include <cuda_runtime.h>
#include <cuda_bf16.h>

// InfoNCE loss (fused gather + dot + log-softmax + mean).
//   inputs: embeddings f32 [100000,128], targets i32 [16384],
//           contexts i32 [16384], negatives i32 [16384,20]
//   output: scalar f32 loss
//
// One warp per batch element, 64-thread blocks (2 warps): 37 regs x 64 thr
// -> 27 blocks/SM = 54 warps (vs 48 with 256-thr blocks), and 8192 blocks
// give a 4x finer end-of-kernel tail. No smem/block reduce: each warp's
// lane 0 fires one unused-result atomicAdd (REDG, fire-and-forget).
// Lane l holds float4 [4l,4l+4) of each row (coalesced 512B warp gathers).
// All 21 logits reduced with a multi-value transpose butterfly (23 shuffles),
// leaving lane l with logit bitrev5(l); one exp per lane.

#define BATCH   16384
#define NUM_NEG 20
#define NLOGITS (NUM_NEG + 1)
#define INV_T   (1.0f / 0.07f)
#define FULL    0xFFFFFFFFu
#define WPB     2
#define GRID    (BATCH / WPB)   // 8192

__global__ void zero_kernel(float* out) {
    out[0] = 0.0f;
}

__global__ __launch_bounds__(64) void infonce_kernel(
    const float* __restrict__ emb,
    const int* __restrict__ targets,
    const int* __restrict__ contexts,
    const int* __restrict__ negatives,
    float* __restrict__ out)
{
    const int lane = threadIdx.x & 31;
    const int warp_in_blk = threadIdx.x >> 5;
    const int b = (blockIdx.x << 1) + warp_in_blk;

    const float4* __restrict__ e4 = (const float4*)emb;

    // target row: lane l -> elements [4l, 4l+4)
    const float4 t = e4[(size_t)targets[b] * 32 + lane];

    // indices: context + 20 negatives (5x int4 broadcast loads; rows are
    // 80B = 5*16B so int4 alignment holds for every b)
    int idx[NLOGITS];
    idx[0] = contexts[b];
    const int4* __restrict__ n4 = (const int4*)(negatives + b * NUM_NEG);
    #pragma unroll
    for (int j = 0; j < 5; j++) {
        const int4 q = n4[j];
        idx[4 * j + 1] = q.x;
        idx[4 * j + 2] = q.y;
        idx[4 * j + 3] = q.z;
        idx[4 * j + 4] = q.w;
    }

    // 21 gathered per-lane partial dots (unrolled -> loads batch up)
    float val[32];
    #pragma unroll
    for (int k = 0; k < NLOGITS; k++) {
        const float4 v = e4[(size_t)idx[k] * 32 + lane];
        val[k] = fmaf(t.x, v.x, fmaf(t.y, v.y, fmaf(t.z, v.z, t.w * v.w)));
    }
    #pragma unroll
    for (int k = NLOGITS; k < 32; k++) val[k] = 0.0f;

    // Multi-value transpose butterfly; all-zero pairs skipped (23 shuffles).
    // After 5 stages lane l holds the warp-summed logit bitrev5(l).
    int live = NLOGITS;
    #pragma unroll
    for (int m = 16; m >= 1; m >>= 1) {
        const int np = (live + 1) >> 1;
        #pragma unroll
        for (int i = 0; i < m; i++) {
            if (i < np) {
                const float a = val[2 * i];
                const float c = val[2 * i + 1];
                const bool hi = (lane & m) != 0;
                const float keep = hi ? c : a;
                const float sent = hi ? a : c;
                val[i] = keep + __shfl_xor_sync(FULL, sent, m);
            } else {
                val[i] = 0.0f;
            }
        }
        live = np;
    }

    const float x = val[0] * INV_T;                 // logit bitrev5(lane)
    const int logit_id = (int)(__brev((unsigned)lane) >> 27);
    const bool valid = logit_id < NLOGITS;

    // warp max over valid lanes
    float xm = valid ? x : -__int_as_float(0x7f800000);
    #pragma unroll
    for (int o = 16; o >= 1; o >>= 1)
        xm = fmaxf(xm, __shfl_xor_sync(FULL, xm, o));

    // warp sum of exp
    float e = valid ? __expf(x - xm) : 0.0f;
    #pragma unroll
    for (int o = 16; o >= 1; o >>= 1)
        e += __shfl_xor_sync(FULL, e, o);

    const float pos = __shfl_sync(FULL, x, 0);      // lane 0 holds logit 0
    const float loss = (xm + __logf(e) - pos) * (1.0f / (float)BATCH);

    // one fire-and-forget REDG per warp (result unused -> no wait)
    if (lane == 0)
        atomicAdd(out, loss);
}

extern "C" void kernel_launch(void* const* d_in, const int* in_sizes, int n_in,
                              void* d_out, int out_size) {
    const float* emb = (const float*)d_in[0];
    const int*   tgt = (const int*)d_in[1];
    const int*   ctx = (const int*)d_in[2];
    const int*   neg = (const int*)d_in[3];
    float* out = (float*)d_out;

    zero_kernel<<<1, 1>>>(out);
    infonce_kernel<<<GRID, WPB * 32>>>(emb, tgt, ctx, neg, out);
}

// round 10
// speedup vs baseline: 1.8847x; 1.8847x over previous
#include <cuda_runtime.h>
#include <cuda_bf16.h>

// InfoNCE loss (fused gather + dot + log-softmax + mean).
//   inputs: embeddings f32 [100000,128], targets i32 [16384],
//           contexts i32 [16384], negatives i32 [16384,20]
//   output: scalar f32 loss
//
// R4 body, 128-thread blocks (4 warps): 37 regs -> 13 CTAs/SM = 52 warps
// (81% occ) vs 48 warps at 256 thr; 4096 blocks = finer tail, still only
// 4096 fire-and-forget REDGs (R9 showed 64-thr/16384-CTA config collapses).
// One warp per batch element; lane l holds float4 [4l,4l+4) of each row
// (coalesced 512B warp gathers). All 21 logits reduced with a multi-value
// transpose butterfly (23 shuffles), leaving lane l with logit bitrev5(l);
// one exp per lane.

#define BATCH   16384
#define NUM_NEG 20
#define NLOGITS (NUM_NEG + 1)
#define INV_T   (1.0f / 0.07f)
#define FULL    0xFFFFFFFFu
#define WPB     4
#define GRID    (BATCH / WPB)   // 4096

__global__ void zero_kernel(float* out) {
    out[0] = 0.0f;
}

__global__ __launch_bounds__(128) void infonce_kernel(
    const float* __restrict__ emb,
    const int* __restrict__ targets,
    const int* __restrict__ contexts,
    const int* __restrict__ negatives,
    float* __restrict__ out)
{
    const int lane = threadIdx.x & 31;
    const int warp_in_blk = threadIdx.x >> 5;
    const int b = (blockIdx.x << 2) + warp_in_blk;

    const float4* __restrict__ e4 = (const float4*)emb;

    // target row: lane l -> elements [4l, 4l+4)
    const float4 t = e4[(size_t)targets[b] * 32 + lane];

    // indices: context + 20 negatives (5x int4 broadcast loads; rows are
    // 80B = 5*16B so int4 alignment holds for every b)
    int idx[NLOGITS];
    idx[0] = contexts[b];
    const int4* __restrict__ n4 = (const int4*)(negatives + b * NUM_NEG);
    #pragma unroll
    for (int j = 0; j < 5; j++) {
        const int4 q = n4[j];
        idx[4 * j + 1] = q.x;
        idx[4 * j + 2] = q.y;
        idx[4 * j + 3] = q.z;
        idx[4 * j + 4] = q.w;
    }

    // 21 gathered per-lane partial dots (unrolled -> loads batch up)
    float val[32];
    #pragma unroll
    for (int k = 0; k < NLOGITS; k++) {
        const float4 v = e4[(size_t)idx[k] * 32 + lane];
        val[k] = fmaf(t.x, v.x, fmaf(t.y, v.y, fmaf(t.z, v.z, t.w * v.w)));
    }
    #pragma unroll
    for (int k = NLOGITS; k < 32; k++) val[k] = 0.0f;

    // Multi-value transpose butterfly; all-zero pairs skipped (23 shuffles).
    // After 5 stages lane l holds the warp-summed logit bitrev5(l).
    int live = NLOGITS;
    #pragma unroll
    for (int m = 16; m >= 1; m >>= 1) {
        const int np = (live + 1) >> 1;
        #pragma unroll
        for (int i = 0; i < m; i++) {
            if (i < np) {
                const float a = val[2 * i];
                const float c = val[2 * i + 1];
                const bool hi = (lane & m) != 0;
                const float keep = hi ? c : a;
                const float sent = hi ? a : c;
                val[i] = keep + __shfl_xor_sync(FULL, sent, m);
            } else {
                val[i] = 0.0f;
            }
        }
        live = np;
    }

    const float x = val[0] * INV_T;                 // logit bitrev5(lane)
    const int logit_id = (int)(__brev((unsigned)lane) >> 27);
    const bool valid = logit_id < NLOGITS;

    // warp max over valid lanes
    float xm = valid ? x : -__int_as_float(0x7f800000);
    #pragma unroll
    for (int o = 16; o >= 1; o >>= 1)
        xm = fmaxf(xm, __shfl_xor_sync(FULL, xm, o));

    // warp sum of exp
    float e = valid ? __expf(x - xm) : 0.0f;
    #pragma unroll
    for (int o = 16; o >= 1; o >>= 1)
        e += __shfl_xor_sync(FULL, e, o);

    const float pos = __shfl_sync(FULL, x, 0);      // lane 0 holds logit 0
    const float loss = (xm + __logf(e) - pos) * (1.0f / (float)BATCH);

    // block reduce: 4 warps -> smem -> one fire-and-forget REDG per block
    __shared__ float part[WPB];
    if (lane == 0) part[warp_in_blk] = loss;
    __syncthreads();
    if (threadIdx.x == 0) {
        float tot = 0.0f;
        #pragma unroll
        for (int w = 0; w < WPB; w++) tot += part[w];
        atomicAdd(out, tot);   // result unused -> REDG, no wait
    }
}

extern "C" void kernel_launch(void* const* d_in, const int* in_sizes, int n_in,
                              void* d_out, int out_size) {
    const float* emb = (const float*)d_in[0];
    const int*   tgt = (const int*)d_in[1];
    const int*   ctx = (const int*)d_in[2];
    const int*   neg = (const int*)d_in[3];
    float* out = (float*)d_out;

    zero_kernel<<<1, 1>>>(out);
    infonce_kernel<<<GRID, WPB * 32>>>(emb, tgt, ctx, neg, out);
}